// round 7
// baseline (speedup 1.0000x reference)
#include <cuda_runtime.h>
#include <cuda_fp16.h>
#include <cstdint>

// ---------------------------------------------------------------------------
// Device scratch (allocation-free)
// ---------------------------------------------------------------------------
__device__ __align__(256) __half g_xh[256 * 1024];
__device__ __align__(256) float g_vp[2 * 256 * 1024];  // partial v (+bias in z=0)
__device__ __align__(256) float g_sp[64 * 256];        // partial dots

// ---------------------------------------------------------------------------
// Helpers
// ---------------------------------------------------------------------------
__device__ __forceinline__ uint32_t smem_u32(const void* p) {
    uint32_t a;
    asm("{ .reg .u64 t; cvta.to.shared.u64 t, %1; cvt.u32.u64 %0, t; }"
        : "=r"(a) : "l"(p));
    return a;
}

__device__ __forceinline__ void cpa16(uint32_t dst, const void* src) {
    asm volatile("cp.async.cg.shared.global [%0], [%1], 16;"
                 :: "r"(dst), "l"(src) : "memory");
}

__device__ __forceinline__ void ldsm_x4(uint32_t* r, uint32_t addr) {
    asm volatile("ldmatrix.sync.aligned.m8n8.x4.shared.b16 {%0,%1,%2,%3}, [%4];"
                 : "=r"(r[0]), "=r"(r[1]), "=r"(r[2]), "=r"(r[3])
                 : "r"(addr));
}

__device__ __forceinline__ void sts128(uint32_t addr, uint4 v) {
    asm volatile("st.shared.v4.b32 [%0], {%1,%2,%3,%4};"
                 :: "r"(addr), "r"(v.x), "r"(v.y), "r"(v.z), "r"(v.w) : "memory");
}

__device__ __forceinline__ void mma16816(float* d, const uint32_t* a,
                                         uint32_t b0, uint32_t b1) {
    asm volatile(
        "mma.sync.aligned.m16n8k16.row.col.f32.f16.f16.f32 "
        "{%0,%1,%2,%3}, {%4,%5,%6,%7}, {%8,%9}, {%0,%1,%2,%3};"
        : "+f"(d[0]), "+f"(d[1]), "+f"(d[2]), "+f"(d[3])
        : "r"(a[0]), "r"(a[1]), "r"(a[2]), "r"(a[3]), "r"(b0), "r"(b1));
}

__device__ __forceinline__ uint4 pack_hi8(const float4 a0, const float4 a1) {
    __half2 h0 = __floats2half2_rn(a0.x, a0.y);
    __half2 h1 = __floats2half2_rn(a0.z, a0.w);
    __half2 h2 = __floats2half2_rn(a1.x, a1.y);
    __half2 h3 = __floats2half2_rn(a1.z, a1.w);
    uint4 u;
    u.x = *reinterpret_cast<uint32_t*>(&h0);
    u.y = *reinterpret_cast<uint32_t*>(&h1);
    u.z = *reinterpret_cast<uint32_t*>(&h2);
    u.w = *reinterpret_cast<uint32_t*>(&h3);
    return u;
}

// ---------------------------------------------------------------------------
// 1) Convert x only: fp32 -> fp16. 128 blocks x 256 threads, 8 floats each.
// ---------------------------------------------------------------------------
__global__ __launch_bounds__(256) void convert_x_kernel(const float* __restrict__ x) {
    const int gid = blockIdx.x * 256 + threadIdx.x;   // 0..32767
    float4 a0 = reinterpret_cast<const float4*>(x)[gid * 2 + 0];
    float4 a1 = reinterpret_cast<const float4*>(x)[gid * 2 + 1];
    reinterpret_cast<uint4*>(g_xh)[gid] = pack_hi8(a0, a1);
}

// ---------------------------------------------------------------------------
// 2) GEMM: A (x fp16) via 3-stage cp.async; B (W) loaded fp32 from global,
//    converted in registers, STS fp16 (double-buffered).
//    CTA: 64(M) x 64(N), 4 warps of 32x32. Grid (32, 4, 2), split-K 2.
// ---------------------------------------------------------------------------
#define A_STAGE_B 8192
#define B_STAGE_B 8192

__global__ void __launch_bounds__(128, 2)
gemm_kernel(const float* __restrict__ q, const float* __restrict__ bias,
            const float* __restrict__ W32) {
    __shared__ __align__(1024) char smemA[3 * A_STAGE_B];
    __shared__ __align__(1024) char smemB[2 * B_STAGE_B];
    const uint32_t sbA = smem_u32(smemA);
    const uint32_t sbB = smem_u32(smemB);

    const int tid  = threadIdx.x;
    const int lane = tid & 31;
    const int wid  = tid >> 5;            // 0..3
    const int wy   = wid >> 1;            // warp m index (0/1)
    const int wx   = wid & 1;             // warp n index (0/1)
    const int gq   = lane >> 2;           // group id 0..7
    const int tq   = lane & 3;            // quad thread 0..3

    const int n0 = blockIdx.x * 64;       // 0..2047
    const int m0 = blockIdx.y * 64;       // 0..255
    const int z  = blockIdx.z;            // split-K half
    const int c0 = z * 8;

    // B loader thread mapping: 4 units of 16B fp16 per thread
    const int br = tid >> 1;                       // rows tid/2*? -> u = tid + 128*s
    (void)br;

    // A loader: 512 16B units, 4 per thread
    auto load_A = [&](int c, int buf) {
        const int koff = c * 64;
        const uint32_t base = sbA + buf * A_STAGE_B;
        #pragma unroll
        for (int s = 0; s < 4; s++) {
            int u = tid + 128 * s;
            int r = u >> 3, j = u & 7;
            uint32_t swz = (uint32_t)((j ^ (r & 7)) << 4);
            cpa16(base + r * 128 + swz, g_xh + (m0 + r) * 1024 + koff + j * 8);
        }
        asm volatile("cp.async.commit_group;" ::: "memory");
    };

    // B register prefetch: 8 float4 per thread (2 per 16B-fp16 unit)
    float4 breg[4][2];
    auto ldg_B = [&](int c) {
        const int koff = c * 64;
        #pragma unroll
        for (int s = 0; s < 4; s++) {
            int u = tid + 128 * s;
            int r = u >> 3, j = u & 7;
            const float4* src = reinterpret_cast<const float4*>(
                W32 + (n0 + r) * 1024 + koff + j * 8);
            breg[s][0] = src[0];
            breg[s][1] = src[1];
        }
    };

    auto sts_B = [&](int buf) {
        const uint32_t base = sbB + buf * B_STAGE_B;
        #pragma unroll
        for (int s = 0; s < 4; s++) {
            int u = tid + 128 * s;
            int r = u >> 3, j = u & 7;
            uint32_t swz = (uint32_t)((j ^ (r & 7)) << 4);
            sts128(base + r * 128 + swz, pack_hi8(breg[s][0], breg[s][1]));
        }
    };

    float acc[2][4][4];
    #pragma unroll
    for (int mi = 0; mi < 2; mi++)
        #pragma unroll
        for (int nj = 0; nj < 4; nj++)
            #pragma unroll
            for (int e = 0; e < 4; e++)
                acc[mi][nj][e] = 0.0f;

    // Prologue
    ldg_B(c0 + 0);
    load_A(c0 + 0, 0);
    load_A(c0 + 1, 1);
    load_A(c0 + 2, 2);

    const int lrow = lane & 15;
    const int lcb  = lane >> 4;

    for (int i = 0; i < 8; i++) {
        const int bufA = i % 3;
        const int bufB = i & 1;

        sts_B(bufB);                       // B_i regs -> smem
        if (i + 1 < 8) ldg_B(c0 + i + 1);  // prefetch B_{i+1} (covers wait+sync+MMA)

        asm volatile("cp.async.wait_group 2;" ::: "memory");
        __syncthreads();                   // A_i + B_i visible

        const uint32_t sa = sbA + bufA * A_STAGE_B;
        const uint32_t sB = sbB + bufB * B_STAGE_B;

        #pragma unroll
        for (int ks = 0; ks < 4; ks++) {
            const int j = ks * 2 + lcb;
            uint32_t a[2][4], b[2][4];
            #pragma unroll
            for (int mi = 0; mi < 2; mi++) {
                int r = wy * 32 + mi * 16 + lrow;
                ldsm_x4(a[mi], sa + r * 128 + ((j ^ (r & 7)) << 4));
            }
            #pragma unroll
            for (int nb = 0; nb < 2; nb++) {
                int r = wx * 32 + nb * 16 + lrow;
                ldsm_x4(b[nb], sB + r * 128 + ((j ^ (r & 7)) << 4));
            }
            #pragma unroll
            for (int mi = 0; mi < 2; mi++)
                #pragma unroll
                for (int nj = 0; nj < 4; nj++) {
                    const int nb = nj >> 1, sub = nj & 1;
                    mma16816(acc[mi][nj], a[mi], b[nb][sub], b[nb][sub + 2]);
                }
        }
        __syncthreads();                   // A bufA free, B bufB free
        if (i + 3 < 8) load_A(c0 + i + 3, bufA);
        else asm volatile("cp.async.commit_group;" ::: "memory");
    }

    // ------------------------------------------------------------------
    // Fused epilogue. acc element (mi, nj, e):
    //   row = m0 + wy*32 + mi*16 + gq + (e>=2 ? 8 : 0)
    //   col = n0 + wx*32 + nj*8  + 2*tq + (e&1)
    // Bias added only by the z==0 half.
    // ------------------------------------------------------------------
    float2 bb[4];
    #pragma unroll
    for (int nj = 0; nj < 4; nj++) {
        if (z == 0) {
            const int col = n0 + wx * 32 + nj * 8 + 2 * tq;
            bb[nj] = *reinterpret_cast<const float2*>(bias + col);
        } else {
            bb[nj].x = 0.0f; bb[nj].y = 0.0f;
        }
    }

    if (n0 < 1024) {
        // k half: partial dot with q per row
        float part[4];
        #pragma unroll
        for (int mi = 0; mi < 2; mi++)
            #pragma unroll
            for (int rh = 0; rh < 2; rh++) {
                const int row = m0 + wy * 32 + mi * 16 + rh * 8 + gq;
                float s = 0.0f;
                #pragma unroll
                for (int nj = 0; nj < 4; nj++) {
                    const int col = n0 + wx * 32 + nj * 8 + 2 * tq;
                    float2 qq = *reinterpret_cast<const float2*>(q + row * 1024 + col);
                    s += (acc[mi][nj][rh * 2 + 0] + bb[nj].x) * qq.x;
                    s += (acc[mi][nj][rh * 2 + 1] + bb[nj].y) * qq.y;
                }
                part[mi * 2 + rh] = s;
            }
        #pragma unroll
        for (int sl = 0; sl < 4; sl++) {
            part[sl] += __shfl_xor_sync(0xFFFFFFFFu, part[sl], 1);
            part[sl] += __shfl_xor_sync(0xFFFFFFFFu, part[sl], 2);
        }
        if (tq == 0) {
            const int slot = z * 32 + blockIdx.x * 2 + wx;   // 0..63
            #pragma unroll
            for (int sl = 0; sl < 4; sl++) {
                const int row = m0 + wy * 32 + (sl >> 1) * 16 + (sl & 1) * 8 + gq;
                g_sp[slot * 256 + row] = part[sl];
            }
        }
    } else {
        // v half: write partial v (+bias for z=0)
        float* vbase = g_vp + z * 256 * 1024;
        #pragma unroll
        for (int mi = 0; mi < 2; mi++)
            #pragma unroll
            for (int rh = 0; rh < 2; rh++) {
                const int row = m0 + wy * 32 + mi * 16 + rh * 8 + gq;
                #pragma unroll
                for (int nj = 0; nj < 4; nj++) {
                    const int col = (n0 - 1024) + wx * 32 + nj * 8 + 2 * tq;
                    float2 o;
                    o.x = acc[mi][nj][rh * 2 + 0] + bb[nj].x;
                    o.y = acc[mi][nj][rh * 2 + 1] + bb[nj].y;
                    *reinterpret_cast<float2*>(vbase + row * 1024 + col) = o;
                }
            }
    }
}

// ---------------------------------------------------------------------------
// 3) Scale: out[b,:] = (v0[b,:]+v1[b,:]) * sum(partials[b])
// ---------------------------------------------------------------------------
__global__ __launch_bounds__(256) void scale_kernel(float* __restrict__ out) {
    const int b = blockIdx.x;
    const int t = threadIdx.x;
    float s = 0.0f;
    #pragma unroll
    for (int j = 0; j < 64; j++) s += g_sp[j * 256 + b];
    float4 v0 = reinterpret_cast<const float4*>(g_vp + b * 1024)[t];
    float4 v1 = reinterpret_cast<const float4*>(g_vp + 256 * 1024 + b * 1024)[t];
    float4 o;
    o.x = (v0.x + v1.x) * s;
    o.y = (v0.y + v1.y) * s;
    o.z = (v0.z + v1.z) * s;
    o.w = (v0.w + v1.w) * s;
    reinterpret_cast<float4*>(out + b * 1024)[t] = o;
}

// ---------------------------------------------------------------------------
extern "C" void kernel_launch(void* const* d_in, const int* in_sizes, int n_in,
                              void* d_out, int out_size) {
    const float* x  = (const float*)d_in[0];   // 256x1024
    const float* q  = (const float*)d_in[1];   // 256x1024
    const float* W  = (const float*)d_in[2];   // 2048x1024
    const float* bs = (const float*)d_in[3];   // 2048
    float* out = (float*)d_out;                // 256x1024

    convert_x_kernel<<<128, 256>>>(x);
    gemm_kernel<<<dim3(32, 4, 2), 128>>>(q, bs, W);
    scale_kernel<<<256, 256>>>(out);
}

// round 8
// speedup vs baseline: 1.0447x; 1.0447x over previous
#include <cuda_runtime.h>
#include <cuda_fp16.h>
#include <cstdint>

// ---------------------------------------------------------------------------
// Device scratch (allocation-free)
// ---------------------------------------------------------------------------
__device__ __align__(256) float g_vp[2 * 256 * 1024];  // partial v (+bias in z=0)
__device__ __align__(256) float g_sp[64 * 256];        // partial dots

// ---------------------------------------------------------------------------
// Helpers
// ---------------------------------------------------------------------------
__device__ __forceinline__ uint32_t smem_u32(const void* p) {
    uint32_t a;
    asm("{ .reg .u64 t; cvta.to.shared.u64 t, %1; cvt.u32.u64 %0, t; }"
        : "=r"(a) : "l"(p));
    return a;
}

__device__ __forceinline__ void ldsm_x4(uint32_t* r, uint32_t addr) {
    asm volatile("ldmatrix.sync.aligned.m8n8.x4.shared.b16 {%0,%1,%2,%3}, [%4];"
                 : "=r"(r[0]), "=r"(r[1]), "=r"(r[2]), "=r"(r[3])
                 : "r"(addr));
}

__device__ __forceinline__ void sts128(uint32_t addr, uint4 v) {
    asm volatile("st.shared.v4.b32 [%0], {%1,%2,%3,%4};"
                 :: "r"(addr), "r"(v.x), "r"(v.y), "r"(v.z), "r"(v.w) : "memory");
}

__device__ __forceinline__ void mma16816(float* d, const uint32_t* a,
                                         uint32_t b0, uint32_t b1) {
    asm volatile(
        "mma.sync.aligned.m16n8k16.row.col.f32.f16.f16.f32 "
        "{%0,%1,%2,%3}, {%4,%5,%6,%7}, {%8,%9}, {%0,%1,%2,%3};"
        : "+f"(d[0]), "+f"(d[1]), "+f"(d[2]), "+f"(d[3])
        : "r"(a[0]), "r"(a[1]), "r"(a[2]), "r"(a[3]), "r"(b0), "r"(b1));
}

__device__ __forceinline__ uint4 pack_hi8(const float4 a0, const float4 a1) {
    __half2 h0 = __floats2half2_rn(a0.x, a0.y);
    __half2 h1 = __floats2half2_rn(a0.z, a0.w);
    __half2 h2 = __floats2half2_rn(a1.x, a1.y);
    __half2 h3 = __floats2half2_rn(a1.z, a1.w);
    uint4 u;
    u.x = *reinterpret_cast<uint32_t*>(&h0);
    u.y = *reinterpret_cast<uint32_t*>(&h1);
    u.z = *reinterpret_cast<uint32_t*>(&h2);
    u.w = *reinterpret_cast<uint32_t*>(&h3);
    return u;
}

// ---------------------------------------------------------------------------
// 1) GEMM: both A (x) and B (W) loaded fp32 from global, converted fp16 in
//    registers, STS to double-buffered smem. No separate convert kernel.
//    CTA: 64(M) x 64(N), 4 warps of 32x32. Grid (32, 4, 2), split-K 2.
// ---------------------------------------------------------------------------
#define A_STAGE_B 8192
#define B_STAGE_B 8192

__global__ void __launch_bounds__(128, 2)
gemm_kernel(const float* __restrict__ x32, const float* __restrict__ q,
            const float* __restrict__ bias, const float* __restrict__ W32) {
    __shared__ __align__(1024) char smemA[2 * A_STAGE_B];
    __shared__ __align__(1024) char smemB[2 * B_STAGE_B];
    const uint32_t sbA = smem_u32(smemA);
    const uint32_t sbB = smem_u32(smemB);

    const int tid  = threadIdx.x;
    const int lane = tid & 31;
    const int wid  = tid >> 5;            // 0..3
    const int wy   = wid >> 1;            // warp m index (0/1)
    const int wx   = wid & 1;             // warp n index (0/1)
    const int gq   = lane >> 2;           // group id 0..7
    const int tq   = lane & 3;            // quad thread 0..3

    const int n0 = blockIdx.x * 64;       // 0..2047
    const int m0 = blockIdx.y * 64;       // 0..255
    const int z  = blockIdx.z;            // split-K half
    const int c0 = z * 8;

    // loader mapping: unit u = tid + 128*s ; r = u>>3 (row 0..63), j = u&7
    // each unit covers 8 consecutive k (8 halves = 16B in smem, 32B fp32 in gmem)

    float4 areg[4][2], breg[4][2];
    auto ldg_AB = [&](int c) {
        const int koff = c * 64;
        #pragma unroll
        for (int s = 0; s < 4; s++) {
            int u = tid + 128 * s;
            int r = u >> 3, j = u & 7;
            const float4* sa = reinterpret_cast<const float4*>(
                x32 + (m0 + r) * 1024 + koff + j * 8);
            const float4* sb = reinterpret_cast<const float4*>(
                W32 + (n0 + r) * 1024 + koff + j * 8);
            areg[s][0] = sa[0];
            areg[s][1] = sa[1];
            breg[s][0] = sb[0];
            breg[s][1] = sb[1];
        }
    };

    auto sts_AB = [&](int buf) {
        const uint32_t baseA = sbA + buf * A_STAGE_B;
        const uint32_t baseB = sbB + buf * B_STAGE_B;
        #pragma unroll
        for (int s = 0; s < 4; s++) {
            int u = tid + 128 * s;
            int r = u >> 3, j = u & 7;
            uint32_t swz = (uint32_t)((j ^ (r & 7)) << 4);
            sts128(baseA + r * 128 + swz, pack_hi8(areg[s][0], areg[s][1]));
            sts128(baseB + r * 128 + swz, pack_hi8(breg[s][0], breg[s][1]));
        }
    };

    float acc[2][4][4];
    #pragma unroll
    for (int mi = 0; mi < 2; mi++)
        #pragma unroll
        for (int nj = 0; nj < 4; nj++)
            #pragma unroll
            for (int e = 0; e < 4; e++)
                acc[mi][nj][e] = 0.0f;

    ldg_AB(c0 + 0);

    const int lrow = lane & 15;
    const int lcb  = lane >> 4;

    for (int i = 0; i < 8; i++) {
        const int buf = i & 1;

        sts_AB(buf);                       // chunk i regs -> smem
        if (i + 1 < 8) ldg_AB(c0 + i + 1); // prefetch next (hidden under sync+MMA)

        __syncthreads();                   // smem chunk i visible

        const uint32_t sa = sbA + buf * A_STAGE_B;
        const uint32_t sB = sbB + buf * B_STAGE_B;

        #pragma unroll
        for (int ks = 0; ks < 4; ks++) {
            const int j = ks * 2 + lcb;
            uint32_t a[2][4], b[2][4];
            #pragma unroll
            for (int mi = 0; mi < 2; mi++) {
                int r = wy * 32 + mi * 16 + lrow;
                ldsm_x4(a[mi], sa + r * 128 + ((j ^ (r & 7)) << 4));
            }
            #pragma unroll
            for (int nb = 0; nb < 2; nb++) {
                int r = wx * 32 + nb * 16 + lrow;
                ldsm_x4(b[nb], sB + r * 128 + ((j ^ (r & 7)) << 4));
            }
            #pragma unroll
            for (int mi = 0; mi < 2; mi++)
                #pragma unroll
                for (int nj = 0; nj < 4; nj++) {
                    const int nb = nj >> 1, sub = nj & 1;
                    mma16816(acc[mi][nj], a[mi], b[nb][sub], b[nb][sub + 2]);
                }
        }
        __syncthreads();                   // buf free for i+2
    }

    // ------------------------------------------------------------------
    // Fused epilogue. acc element (mi, nj, e):
    //   row = m0 + wy*32 + mi*16 + gq + (e>=2 ? 8 : 0)
    //   col = n0 + wx*32 + nj*8  + 2*tq + (e&1)
    // Bias added only by the z==0 half.
    // ------------------------------------------------------------------
    float2 bb[4];
    #pragma unroll
    for (int nj = 0; nj < 4; nj++) {
        if (z == 0) {
            const int col = n0 + wx * 32 + nj * 8 + 2 * tq;
            bb[nj] = *reinterpret_cast<const float2*>(bias + col);
        } else {
            bb[nj].x = 0.0f; bb[nj].y = 0.0f;
        }
    }

    if (n0 < 1024) {
        // k half: partial dot with q per row
        float part[4];
        #pragma unroll
        for (int mi = 0; mi < 2; mi++)
            #pragma unroll
            for (int rh = 0; rh < 2; rh++) {
                const int row = m0 + wy * 32 + mi * 16 + rh * 8 + gq;
                float s = 0.0f;
                #pragma unroll
                for (int nj = 0; nj < 4; nj++) {
                    const int col = n0 + wx * 32 + nj * 8 + 2 * tq;
                    float2 qq = *reinterpret_cast<const float2*>(q + row * 1024 + col);
                    s += (acc[mi][nj][rh * 2 + 0] + bb[nj].x) * qq.x;
                    s += (acc[mi][nj][rh * 2 + 1] + bb[nj].y) * qq.y;
                }
                part[mi * 2 + rh] = s;
            }
        #pragma unroll
        for (int sl = 0; sl < 4; sl++) {
            part[sl] += __shfl_xor_sync(0xFFFFFFFFu, part[sl], 1);
            part[sl] += __shfl_xor_sync(0xFFFFFFFFu, part[sl], 2);
        }
        if (tq == 0) {
            const int slot = z * 32 + blockIdx.x * 2 + wx;   // 0..63
            #pragma unroll
            for (int sl = 0; sl < 4; sl++) {
                const int row = m0 + wy * 32 + (sl >> 1) * 16 + (sl & 1) * 8 + gq;
                g_sp[slot * 256 + row] = part[sl];
            }
        }
    } else {
        // v half: write partial v (+bias for z=0)
        float* vbase = g_vp + z * 256 * 1024;
        #pragma unroll
        for (int mi = 0; mi < 2; mi++)
            #pragma unroll
            for (int rh = 0; rh < 2; rh++) {
                const int row = m0 + wy * 32 + mi * 16 + rh * 8 + gq;
                #pragma unroll
                for (int nj = 0; nj < 4; nj++) {
                    const int col = (n0 - 1024) + wx * 32 + nj * 8 + 2 * tq;
                    float2 o;
                    o.x = acc[mi][nj][rh * 2 + 0] + bb[nj].x;
                    o.y = acc[mi][nj][rh * 2 + 1] + bb[nj].y;
                    *reinterpret_cast<float2*>(vbase + row * 1024 + col) = o;
                }
            }
    }
}

// ---------------------------------------------------------------------------
// 2) Scale: out[b,:] = (v0[b,:]+v1[b,:]) * sum(partials[b])
//    Block-wide reduce of the 64 partials (one load per thread).
// ---------------------------------------------------------------------------
__global__ __launch_bounds__(256) void scale_kernel(float* __restrict__ out) {
    const int b = blockIdx.x;
    const int t = threadIdx.x;
    const int w = t >> 5, l = t & 31;

    __shared__ float red[8];
    __shared__ float s_tot;
    float p = (t < 64) ? g_sp[t * 256 + b] : 0.0f;
    #pragma unroll
    for (int off = 16; off > 0; off >>= 1)
        p += __shfl_xor_sync(0xFFFFFFFFu, p, off);
    if (l == 0) red[w] = p;
    __syncthreads();
    if (w == 0) {
        float v = (l < 8) ? red[l] : 0.0f;
        #pragma unroll
        for (int off = 4; off > 0; off >>= 1)
            v += __shfl_xor_sync(0xFFFFFFFFu, v, off);
        if (l == 0) s_tot = v;
    }
    __syncthreads();
    const float s = s_tot;

    float4 v0 = reinterpret_cast<const float4*>(g_vp + b * 1024)[t];
    float4 v1 = reinterpret_cast<const float4*>(g_vp + 256 * 1024 + b * 1024)[t];
    float4 o;
    o.x = (v0.x + v1.x) * s;
    o.y = (v0.y + v1.y) * s;
    o.z = (v0.z + v1.z) * s;
    o.w = (v0.w + v1.w) * s;
    reinterpret_cast<float4*>(out + b * 1024)[t] = o;
}

// ---------------------------------------------------------------------------
extern "C" void kernel_launch(void* const* d_in, const int* in_sizes, int n_in,
                              void* d_out, int out_size) {
    const float* x  = (const float*)d_in[0];   // 256x1024
    const float* q  = (const float*)d_in[1];   // 256x1024
    const float* W  = (const float*)d_in[2];   // 2048x1024
    const float* bs = (const float*)d_in[3];   // 2048
    float* out = (float*)d_out;                // 256x1024

    gemm_kernel<<<dim3(32, 4, 2), 128>>>(x, q, bs, W);
    scale_kernel<<<256, 256>>>(out);
}